// round 1
// baseline (speedup 1.0000x reference)
#include <cuda_runtime.h>
#include <cuda_bf16.h>

#define NN 100000
#define DIMV 64
#define EE 1600000

// Scratch (allocation-free rule: __device__ globals)
__device__ float g_deg[NN];
__device__ float g_norm[NN];
__device__ float g_tmp[NN * DIMV];   // h_cur * norm (message source)
__device__ float g_acc[NN * DIMV];   // segment-sum accumulator

// ---------------------------------------------------------------------------
// K0: zero g_deg and g_acc (grid-stride)
// ---------------------------------------------------------------------------
__global__ void k_zero() {
    const int total = NN * DIMV + NN;
    for (int i = blockIdx.x * blockDim.x + threadIdx.x; i < total;
         i += gridDim.x * blockDim.x) {
        if (i < NN * DIMV) g_acc[i] = 0.0f;
        else               g_deg[i - NN * DIMV] = 0.0f;
    }
}

// ---------------------------------------------------------------------------
// K1: weighted in-degree: g_deg[dst[e]] += w[e]
// ---------------------------------------------------------------------------
__global__ void k_degree(const float* __restrict__ w,
                         const int* __restrict__ dst, int E) {
    int e = blockIdx.x * blockDim.x + threadIdx.x;
    if (e < E) atomicAdd(&g_deg[dst[e]], w[e]);
}

// ---------------------------------------------------------------------------
// K2: norm = rsqrt(max(deg,1)); out = h/3; tmp = h*norm
// One thread per (node, 4 dims): 16 threads per node, float4 path.
// ---------------------------------------------------------------------------
__global__ void k_init(const float* __restrict__ h, float* __restrict__ out,
                       int N) {
    int t = blockIdx.x * blockDim.x + threadIdx.x;        // t in [0, N*16)
    if (t >= N * (DIMV / 4)) return;
    int node = t >> 4;             // /16
    int q    = t & 15;             // which float4 of the row
    float nrm = rsqrtf(fmaxf(g_deg[node], 1.0f));
    if (q == 0) g_norm[node] = nrm;
    int idx = node * DIMV + q * 4;
    float4 hv = *(const float4*)&h[idx];
    float4 ov, tv;
    const float third = 1.0f / 3.0f;
    ov.x = hv.x * third; ov.y = hv.y * third;
    ov.z = hv.z * third; ov.w = hv.w * third;
    tv.x = hv.x * nrm;   tv.y = hv.y * nrm;
    tv.z = hv.z * nrm;   tv.w = hv.w * nrm;
    *(float4*)&out[idx]   = ov;
    *(float4*)&g_tmp[idx] = tv;
}

// ---------------------------------------------------------------------------
// K3: edge scatter. Warp per edge, float2 per lane.
//     g_acc[dst] += g_tmp[src] * w[e]
// ---------------------------------------------------------------------------
__global__ void k_scatter(const float* __restrict__ w,
                          const int* __restrict__ src,
                          const int* __restrict__ dst, int E) {
    int t = blockIdx.x * blockDim.x + threadIdx.x;
    int e = t >> 5;
    if (e >= E) return;
    int lane = t & 31;
    float we = __ldg(&w[e]);
    int s = __ldg(&src[e]);
    int d = __ldg(&dst[e]);
    float2 v = *(const float2*)&g_tmp[s * DIMV + lane * 2];
    float* dstp = &g_acc[d * DIMV + lane * 2];
    atomicAdd(dstp,     v.x * we);
    atomicAdd(dstp + 1, v.y * we);
}

// ---------------------------------------------------------------------------
// K4: layer epilogue. v = acc*norm; out += v/3;
//     if !LAST: tmp = v*norm (next layer's source), acc = 0 (reset in-pass).
// ---------------------------------------------------------------------------
template <bool LAST>
__global__ void k_epilogue(float* __restrict__ out, int N) {
    int t = blockIdx.x * blockDim.x + threadIdx.x;
    if (t >= N * (DIMV / 4)) return;
    int node = t >> 4;
    int q    = t & 15;
    float nrm = g_norm[node];
    int idx = node * DIMV + q * 4;
    float4 a = *(const float4*)&g_acc[idx];
    float4 v;
    v.x = a.x * nrm; v.y = a.y * nrm; v.z = a.z * nrm; v.w = a.w * nrm;
    const float third = 1.0f / 3.0f;
    float4 o = *(const float4*)&out[idx];
    o.x += v.x * third; o.y += v.y * third;
    o.z += v.z * third; o.w += v.w * third;
    *(float4*)&out[idx] = o;
    if (!LAST) {
        float4 tv;
        tv.x = v.x * nrm; tv.y = v.y * nrm;
        tv.z = v.z * nrm; tv.w = v.w * nrm;
        *(float4*)&g_tmp[idx] = tv;
        float4 z = {0.0f, 0.0f, 0.0f, 0.0f};
        *(float4*)&g_acc[idx] = z;
    }
}

// ---------------------------------------------------------------------------
// Launch
// ---------------------------------------------------------------------------
extern "C" void kernel_launch(void* const* d_in, const int* in_sizes, int n_in,
                              void* d_out, int out_size) {
    const float* h   = (const float*)d_in[0];
    const float* w   = (const float*)d_in[1];
    const int*   src = (const int*)d_in[2];
    const int*   dst = (const int*)d_in[3];
    float* out = (float*)d_out;

    const int N = in_sizes[0] / DIMV;   // 100000
    const int E = in_sizes[1];          // 1600000

    const int TB = 256;

    // 0) zero deg + acc
    k_zero<<<2048, TB>>>();

    // 1) weighted in-degree
    k_degree<<<(E + TB - 1) / TB, TB>>>(w, dst, E);

    // 2) norm, out = h/3, tmp = h*norm
    int nt_node = N * (DIMV / 4);
    k_init<<<(nt_node + TB - 1) / TB, TB>>>(h, out, N);

    // Layer 1
    long long st = (long long)E * 32;
    int sblocks = (int)((st + TB - 1) / TB);
    k_scatter<<<sblocks, TB>>>(w, src, dst, E);
    k_epilogue<false><<<(nt_node + TB - 1) / TB, TB>>>(out, N);

    // Layer 2
    k_scatter<<<sblocks, TB>>>(w, src, dst, E);
    k_epilogue<true><<<(nt_node + TB - 1) / TB, TB>>>(out, N);
}

// round 3
// speedup vs baseline: 1.6173x; 1.6173x over previous
#include <cuda_runtime.h>
#include <cuda_bf16.h>

#define NN 100000
#define DIMV 64
#define EE 1600000

// Scratch (allocation-free rule: __device__ globals). 256B-aligned so the
// float4 vector atomics / loads are always 16B-aligned.
__device__ __align__(256) float g_deg[NN];
__device__ __align__(256) float g_norm[NN];
__device__ __align__(256) float g_tmp[NN * DIMV];   // h_cur * norm (message source)
__device__ __align__(256) float g_acc[NN * DIMV];   // segment-sum accumulator

// ---------------------------------------------------------------------------
// K0: zero g_deg and g_acc (grid-stride, float4)
// ---------------------------------------------------------------------------
__global__ void k_zero() {
    const int total4 = (NN * DIMV) / 4;
    float4 z = {0.f, 0.f, 0.f, 0.f};
    for (int i = blockIdx.x * blockDim.x + threadIdx.x; i < total4;
         i += gridDim.x * blockDim.x) {
        *(float4*)&g_acc[i * 4] = z;
        if (i < NN) g_deg[i] = 0.0f;
    }
}

// ---------------------------------------------------------------------------
// K1: weighted in-degree: g_deg[dst[e]] += w[e]. 4 edges per thread.
// ---------------------------------------------------------------------------
__global__ void k_degree(const float* __restrict__ w,
                         const int* __restrict__ dst, int E) {
    int t = blockIdx.x * blockDim.x + threadIdx.x;
    int e = t * 4;
    if (e + 3 < E) {
        float4 wv = *(const float4*)&w[e];
        int4   dv = *(const int4*)&dst[e];
        atomicAdd(&g_deg[dv.x], wv.x);
        atomicAdd(&g_deg[dv.y], wv.y);
        atomicAdd(&g_deg[dv.z], wv.z);
        atomicAdd(&g_deg[dv.w], wv.w);
    } else {
        for (; e < E; ++e) atomicAdd(&g_deg[dst[e]], w[e]);
    }
}

// ---------------------------------------------------------------------------
// K2: norm = rsqrt(max(deg,1)); out = h/3; tmp = h*norm
// 16 threads per node, float4 path.
// ---------------------------------------------------------------------------
__global__ void k_init(const float* __restrict__ h, float* __restrict__ out,
                       int N) {
    int t = blockIdx.x * blockDim.x + threadIdx.x;
    if (t >= N * (DIMV / 4)) return;
    int node = t >> 4;
    int q    = t & 15;
    float nrm = rsqrtf(fmaxf(g_deg[node], 1.0f));
    if (q == 0) g_norm[node] = nrm;
    int idx = node * DIMV + q * 4;
    float4 hv = *(const float4*)&h[idx];
    float4 ov, tv;
    const float third = 1.0f / 3.0f;
    ov.x = hv.x * third; ov.y = hv.y * third;
    ov.z = hv.z * third; ov.w = hv.w * third;
    tv.x = hv.x * nrm;   tv.y = hv.y * nrm;
    tv.z = hv.z * nrm;   tv.w = hv.w * nrm;
    *(float4*)&out[idx]   = ov;
    *(float4*)&g_tmp[idx] = tv;
}

// ---------------------------------------------------------------------------
// K3: edge scatter. Half-warp (16 lanes) per edge, float4 per lane.
//     g_acc[dst] += g_tmp[src] * w[e]  via red.global.add.v4.f32
// Per edge: 16 x LDG.128 gather + 16 x REDG.128 (vs 32 LDG.64 + 64 REDG.32).
// ---------------------------------------------------------------------------
__global__ void k_scatter(const float* __restrict__ w,
                          const int* __restrict__ src,
                          const int* __restrict__ dst, int E) {
    int t = blockIdx.x * blockDim.x + threadIdx.x;
    int e = t >> 4;                 // edge index (16 threads per edge)
    if (e >= E) return;
    int q = t & 15;                 // which float4 of the 64-dim row
    float we = __ldg(&w[e]);
    int s = __ldg(&src[e]);
    int d = __ldg(&dst[e]);
    float4 v = *(const float4*)&g_tmp[s * DIMV + q * 4];
    v.x *= we; v.y *= we; v.z *= we; v.w *= we;
    float* dp = &g_acc[d * DIMV + q * 4];
    asm volatile("red.global.add.v4.f32 [%0], {%1, %2, %3, %4};"
                 :: "l"(dp), "f"(v.x), "f"(v.y), "f"(v.z), "f"(v.w)
                 : "memory");
}

// ---------------------------------------------------------------------------
// K4: layer epilogue. v = acc*norm; out += v/3;
//     if !LAST: tmp = v*norm (next layer source), acc = 0 (reset in-pass).
// ---------------------------------------------------------------------------
template <bool LAST>
__global__ void k_epilogue(float* __restrict__ out, int N) {
    int t = blockIdx.x * blockDim.x + threadIdx.x;
    if (t >= N * (DIMV / 4)) return;
    int node = t >> 4;
    int q    = t & 15;
    float nrm = g_norm[node];
    int idx = node * DIMV + q * 4;
    float4 a = *(const float4*)&g_acc[idx];
    float4 v;
    v.x = a.x * nrm; v.y = a.y * nrm; v.z = a.z * nrm; v.w = a.w * nrm;
    const float third = 1.0f / 3.0f;
    float4 o = *(const float4*)&out[idx];
    o.x += v.x * third; o.y += v.y * third;
    o.z += v.z * third; o.w += v.w * third;
    *(float4*)&out[idx] = o;
    if (!LAST) {
        float4 tv;
        tv.x = v.x * nrm; tv.y = v.y * nrm;
        tv.z = v.z * nrm; tv.w = v.w * nrm;
        *(float4*)&g_tmp[idx] = tv;
        float4 z = {0.0f, 0.0f, 0.0f, 0.0f};
        *(float4*)&g_acc[idx] = z;
    }
}

// ---------------------------------------------------------------------------
// Launch
// ---------------------------------------------------------------------------
extern "C" void kernel_launch(void* const* d_in, const int* in_sizes, int n_in,
                              void* d_out, int out_size) {
    const float* h   = (const float*)d_in[0];
    const float* w   = (const float*)d_in[1];
    const int*   src = (const int*)d_in[2];
    const int*   dst = (const int*)d_in[3];
    float* out = (float*)d_out;

    const int N = in_sizes[0] / DIMV;   // 100000
    const int E = in_sizes[1];          // 1600000

    const int TB = 256;

    // 0) zero deg + acc
    k_zero<<<2048, TB>>>();

    // 1) weighted in-degree (4 edges / thread)
    int dthreads = (E + 3) / 4;
    k_degree<<<(dthreads + TB - 1) / TB, TB>>>(w, dst, E);

    // 2) norm, out = h/3, tmp = h*norm
    int nt_node = N * (DIMV / 4);
    k_init<<<(nt_node + TB - 1) / TB, TB>>>(h, out, N);

    // scatter: 16 threads per edge
    long long st = (long long)E * 16;
    int sblocks = (int)((st + TB - 1) / TB);

    // Layer 1
    k_scatter<<<sblocks, TB>>>(w, src, dst, E);
    k_epilogue<false><<<(nt_node + TB - 1) / TB, TB>>>(out, N);

    // Layer 2
    k_scatter<<<sblocks, TB>>>(w, src, dst, E);
    k_epilogue<true><<<(nt_node + TB - 1) / TB, TB>>>(out, N);
}

// round 7
// speedup vs baseline: 2.3336x; 1.4429x over previous
#include <cuda_runtime.h>
#include <cuda_bf16.h>

#define NN 100000
#define DIMV 64
#define EE 1600000
#define CHUNK 512
#define NCHMAX ((NN + CHUNK - 1) / CHUNK)   // 196

// Scratch (__device__ globals per allocation-free rule)
__device__ __align__(256) float  g_deg[NN];
__device__ __align__(256) float  g_norm[NN];
__device__ __align__(256) int    g_cnt[NN];     // in-degree counts
__device__ __align__(256) int    g_off[NN];     // CSR offsets (exclusive scan)
__device__ __align__(256) int    g_fill[NN];    // placement cursors
__device__ __align__(256) int    g_csum[NCHMAX];// chunk sums -> chunk bases
__device__ __align__(256) float2 g_edges[EE];   // dst-sorted {src_bits, w}
__device__ __align__(256) float  g_tmpA[NN * DIMV];
__device__ __align__(256) float  g_tmpB[NN * DIMV];

// ---------------------------------------------------------------------------
// K0: zero deg, cnt, fill
// ---------------------------------------------------------------------------
__global__ void k_zero(int N) {
    for (int i = blockIdx.x * blockDim.x + threadIdx.x; i < N;
         i += gridDim.x * blockDim.x) {
        g_deg[i]  = 0.0f;
        g_cnt[i]  = 0;
        g_fill[i] = 0;
    }
}

// ---------------------------------------------------------------------------
// K1: weighted degree + count histogram (4 edges/thread)
// ---------------------------------------------------------------------------
__global__ void k_degcnt(const float* __restrict__ w,
                         const int* __restrict__ dst, int E) {
    int t = blockIdx.x * blockDim.x + threadIdx.x;
    int e = t * 4;
    if (e + 3 < E) {
        float4 wv = *(const float4*)&w[e];
        int4   dv = *(const int4*)&dst[e];
        atomicAdd(&g_deg[dv.x], wv.x); atomicAdd(&g_cnt[dv.x], 1);
        atomicAdd(&g_deg[dv.y], wv.y); atomicAdd(&g_cnt[dv.y], 1);
        atomicAdd(&g_deg[dv.z], wv.z); atomicAdd(&g_cnt[dv.z], 1);
        atomicAdd(&g_deg[dv.w], wv.w); atomicAdd(&g_cnt[dv.w], 1);
    } else {
        for (; e < E; ++e) {
            atomicAdd(&g_deg[dst[e]], w[e]);
            atomicAdd(&g_cnt[dst[e]], 1);
        }
    }
}

// ---------------------------------------------------------------------------
// Scan step 1: per-chunk sums of g_cnt
// ---------------------------------------------------------------------------
__global__ void k_scan1(int N) {
    __shared__ int sm[CHUNK];
    int b = blockIdx.x, t = threadIdx.x;
    int i = b * CHUNK + t;
    sm[t] = (i < N) ? g_cnt[i] : 0;
    __syncthreads();
    for (int s = CHUNK / 2; s > 0; s >>= 1) {
        if (t < s) sm[t] += sm[t + s];
        __syncthreads();
    }
    if (t == 0) g_csum[b] = sm[0];
}

// ---------------------------------------------------------------------------
// Scan step 2: exclusive scan of chunk sums (single block, nch <= 256)
// ---------------------------------------------------------------------------
__global__ void k_scan2(int nch) {
    __shared__ int sm[256];
    int t = threadIdx.x;
    int v = (t < nch) ? g_csum[t] : 0;
    sm[t] = v;
    __syncthreads();
    // inclusive Hillis-Steele
    for (int d = 1; d < 256; d <<= 1) {
        int add = (t >= d) ? sm[t - d] : 0;
        __syncthreads();
        sm[t] += add;
        __syncthreads();
    }
    if (t < nch) g_csum[t] = sm[t] - v;   // exclusive
}

// ---------------------------------------------------------------------------
// Scan step 3: intra-chunk exclusive scan + chunk base -> g_off
// ---------------------------------------------------------------------------
__global__ void k_scan3(int N) {
    __shared__ int sm[CHUNK];
    int b = blockIdx.x, t = threadIdx.x;
    int i = b * CHUNK + t;
    int x = (i < N) ? g_cnt[i] : 0;
    sm[t] = x;
    __syncthreads();
    for (int d = 1; d < CHUNK; d <<= 1) {
        int add = (t >= d) ? sm[t - d] : 0;
        __syncthreads();
        sm[t] += add;
        __syncthreads();
    }
    if (i < N) g_off[i] = g_csum[b] + sm[t] - x;   // exclusive + base
}

// ---------------------------------------------------------------------------
// K_place: counting-sort edges by dst into g_edges = {src_bits, w}
// ---------------------------------------------------------------------------
__global__ void k_place(const float* __restrict__ w,
                        const int* __restrict__ src,
                        const int* __restrict__ dst, int E) {
    int e = blockIdx.x * blockDim.x + threadIdx.x;
    if (e >= E) return;
    int d = dst[e];
    int p = g_off[d] + atomicAdd(&g_fill[d], 1);
    g_edges[p] = make_float2(__int_as_float(src[e]), w[e]);
}

// ---------------------------------------------------------------------------
// K_init: norm = rsqrt(max(deg,1)); out = h/3; tmpA = h*norm
// ---------------------------------------------------------------------------
__global__ void k_init(const float* __restrict__ h, float* __restrict__ out,
                       int N) {
    int t = blockIdx.x * blockDim.x + threadIdx.x;
    if (t >= N * (DIMV / 4)) return;
    int node = t >> 4;
    int q    = t & 15;
    float nrm = rsqrtf(fmaxf(g_deg[node], 1.0f));
    if (q == 0) g_norm[node] = nrm;
    int idx = node * DIMV + q * 4;
    float4 hv = *(const float4*)&h[idx];
    float4 ov, tv;
    const float third = 1.0f / 3.0f;
    ov.x = hv.x * third; ov.y = hv.y * third;
    ov.z = hv.z * third; ov.w = hv.w * third;
    tv.x = hv.x * nrm;   tv.y = hv.y * nrm;
    tv.z = hv.z * nrm;   tv.w = hv.w * nrm;
    *(float4*)&out[idx]    = ov;
    *(float4*)&g_tmpA[idx] = tv;
}

// ---------------------------------------------------------------------------
// K_gather<LAST>: warp per node. Fused aggregate + epilogue.
//   sum = sum_{e in in(n)} tmp_src[src_e] * w_e        (registers)
//   h   = sum * norm;  out += h/3;  if !LAST: tmpB = h * norm
// ---------------------------------------------------------------------------
template <bool LAST>
__global__ void k_gather(float* __restrict__ out, int N) {
    const float* __restrict__ tsrc = LAST ? g_tmpB : g_tmpA;
    int gw = (blockIdx.x * blockDim.x + threadIdx.x) >> 5;
    if (gw >= N) return;
    int lane = threadIdx.x & 31;
    int off = g_off[gw];
    int dg  = g_cnt[gw];
    float ax = 0.0f, ay = 0.0f;

    for (int base = 0; base < dg; base += 32) {
        int m = dg - base; if (m > 32) m = 32;
        float ex = 0.0f, ey = 0.0f;
        if (lane < m) {
            float2 ed = g_edges[off + base + lane];
            ex = ed.x; ey = ed.y;
        }
        if (m == 32) {
            #pragma unroll
            for (int k = 0; k < 32; k++) {
                int   s  = __float_as_int(__shfl_sync(0xffffffffu, ex, k));
                float sw = __shfl_sync(0xffffffffu, ey, k);
                float2 v = *(const float2*)&tsrc[s * DIMV + lane * 2];
                ax = fmaf(v.x, sw, ax);
                ay = fmaf(v.y, sw, ay);
            }
        } else {
            for (int k = 0; k < m; k++) {
                int   s  = __float_as_int(__shfl_sync(0xffffffffu, ex, k));
                float sw = __shfl_sync(0xffffffffu, ey, k);
                float2 v = *(const float2*)&tsrc[s * DIMV + lane * 2];
                ax = fmaf(v.x, sw, ax);
                ay = fmaf(v.y, sw, ay);
            }
        }
    }

    float nrm = g_norm[gw];
    float hx = ax * nrm, hy = ay * nrm;
    int idx = gw * DIMV + lane * 2;
    const float third = 1.0f / 3.0f;
    float2 o = *(float2*)&out[idx];
    o.x += hx * third; o.y += hy * third;
    *(float2*)&out[idx] = o;
    if (!LAST) {
        *(float2*)&g_tmpB[idx] = make_float2(hx * nrm, hy * nrm);
    }
}

// ---------------------------------------------------------------------------
// Launch
// ---------------------------------------------------------------------------
extern "C" void kernel_launch(void* const* d_in, const int* in_sizes, int n_in,
                              void* d_out, int out_size) {
    const float* h   = (const float*)d_in[0];
    const float* w   = (const float*)d_in[1];
    const int*   src = (const int*)d_in[2];
    const int*   dst = (const int*)d_in[3];
    float* out = (float*)d_out;

    const int N = in_sizes[0] / DIMV;   // 100000
    const int E = in_sizes[1];          // 1600000
    const int nch = (N + CHUNK - 1) / CHUNK;

    const int TB = 256;

    // CSR build
    k_zero<<<256, TB>>>(N);
    int dthreads = (E + 3) / 4;
    k_degcnt<<<(dthreads + TB - 1) / TB, TB>>>(w, dst, E);
    k_scan1<<<nch, CHUNK>>>(N);
    k_scan2<<<1, 256>>>(nch);
    k_scan3<<<nch, CHUNK>>>(N);
    k_place<<<(E + TB - 1) / TB, TB>>>(w, src, dst, E);

    // norm + layer-0 contribution
    int nt_node = N * (DIMV / 4);
    k_init<<<(nt_node + TB - 1) / TB, TB>>>(h, out, N);

    // Layers (warp per node, 8 warps/block)
    int gblocks = (N + 7) / 8;
    k_gather<false><<<gblocks, TB>>>(out, N);   // reads tmpA, writes tmpB
    k_gather<true><<<gblocks, TB>>>(out, N);    // reads tmpB
}

// round 8
// speedup vs baseline: 2.6958x; 1.1552x over previous
#include <cuda_runtime.h>
#include <cuda_fp16.h>
#include <cuda_bf16.h>

#define NN 100000
#define DIMV 64
#define EE 1600000
#define CHUNK 512
#define NCHMAX ((NN + CHUNK - 1) / CHUNK)   // 196

// Scratch (__device__ globals per allocation-free rule)
__device__ __align__(256) float  g_deg[NN];
__device__ __align__(256) float  g_norm[NN];
__device__ __align__(256) int    g_cnt[NN];     // in-degree counts
__device__ __align__(256) int    g_off[NN];     // CSR offsets (exclusive scan)
__device__ __align__(256) int    g_fill[NN];    // placement cursors
__device__ __align__(256) int    g_csum[NCHMAX];// chunk sums -> chunk bases
__device__ __align__(256) float2 g_edges[EE];   // dst-sorted {src_bits, w}
__device__ __align__(256) __half g_tmpA[NN * DIMV];  // h_cur * norm (fp16)
__device__ __align__(256) __half g_tmpB[NN * DIMV];

// ---------------------------------------------------------------------------
// K0: zero deg, cnt, fill
// ---------------------------------------------------------------------------
__global__ void k_zero(int N) {
    for (int i = blockIdx.x * blockDim.x + threadIdx.x; i < N;
         i += gridDim.x * blockDim.x) {
        g_deg[i]  = 0.0f;
        g_cnt[i]  = 0;
        g_fill[i] = 0;
    }
}

// ---------------------------------------------------------------------------
// K1: weighted degree + count histogram (4 edges/thread)
// ---------------------------------------------------------------------------
__global__ void k_degcnt(const float* __restrict__ w,
                         const int* __restrict__ dst, int E) {
    int t = blockIdx.x * blockDim.x + threadIdx.x;
    int e = t * 4;
    if (e + 3 < E) {
        float4 wv = *(const float4*)&w[e];
        int4   dv = *(const int4*)&dst[e];
        atomicAdd(&g_deg[dv.x], wv.x); atomicAdd(&g_cnt[dv.x], 1);
        atomicAdd(&g_deg[dv.y], wv.y); atomicAdd(&g_cnt[dv.y], 1);
        atomicAdd(&g_deg[dv.z], wv.z); atomicAdd(&g_cnt[dv.z], 1);
        atomicAdd(&g_deg[dv.w], wv.w); atomicAdd(&g_cnt[dv.w], 1);
    } else {
        for (; e < E; ++e) {
            atomicAdd(&g_deg[dst[e]], w[e]);
            atomicAdd(&g_cnt[dst[e]], 1);
        }
    }
}

// ---------------------------------------------------------------------------
// Scan step 1: per-chunk sums of g_cnt
// ---------------------------------------------------------------------------
__global__ void k_scan1(int N) {
    __shared__ int sm[CHUNK];
    int b = blockIdx.x, t = threadIdx.x;
    int i = b * CHUNK + t;
    sm[t] = (i < N) ? g_cnt[i] : 0;
    __syncthreads();
    for (int s = CHUNK / 2; s > 0; s >>= 1) {
        if (t < s) sm[t] += sm[t + s];
        __syncthreads();
    }
    if (t == 0) g_csum[b] = sm[0];
}

// ---------------------------------------------------------------------------
// Scan step 2: exclusive scan of chunk sums (single block, nch <= 256)
// ---------------------------------------------------------------------------
__global__ void k_scan2(int nch) {
    __shared__ int sm[256];
    int t = threadIdx.x;
    int v = (t < nch) ? g_csum[t] : 0;
    sm[t] = v;
    __syncthreads();
    for (int d = 1; d < 256; d <<= 1) {
        int add = (t >= d) ? sm[t - d] : 0;
        __syncthreads();
        sm[t] += add;
        __syncthreads();
    }
    if (t < nch) g_csum[t] = sm[t] - v;   // exclusive
}

// ---------------------------------------------------------------------------
// Scan step 3: intra-chunk exclusive scan + chunk base -> g_off
// ---------------------------------------------------------------------------
__global__ void k_scan3(int N) {
    __shared__ int sm[CHUNK];
    int b = blockIdx.x, t = threadIdx.x;
    int i = b * CHUNK + t;
    int x = (i < N) ? g_cnt[i] : 0;
    sm[t] = x;
    __syncthreads();
    for (int d = 1; d < CHUNK; d <<= 1) {
        int add = (t >= d) ? sm[t - d] : 0;
        __syncthreads();
        sm[t] += add;
        __syncthreads();
    }
    if (i < N) g_off[i] = g_csum[b] + sm[t] - x;   // exclusive + base
}

// ---------------------------------------------------------------------------
// K_place: counting-sort edges by dst into g_edges = {src_bits, w}
// ---------------------------------------------------------------------------
__global__ void k_place(const float* __restrict__ w,
                        const int* __restrict__ src,
                        const int* __restrict__ dst, int E) {
    int e = blockIdx.x * blockDim.x + threadIdx.x;
    if (e >= E) return;
    int d = dst[e];
    int p = g_off[d] + atomicAdd(&g_fill[d], 1);
    g_edges[p] = make_float2(__int_as_float(src[e]), w[e]);
}

// ---------------------------------------------------------------------------
// K_init: norm = rsqrt(max(deg,1)); out = h/3; tmpA = half(h*norm)
// ---------------------------------------------------------------------------
__global__ void k_init(const float* __restrict__ h, float* __restrict__ out,
                       int N) {
    int t = blockIdx.x * blockDim.x + threadIdx.x;
    if (t >= N * (DIMV / 4)) return;
    int node = t >> 4;
    int q    = t & 15;
    float nrm = rsqrtf(fmaxf(g_deg[node], 1.0f));
    if (q == 0) g_norm[node] = nrm;
    int idx = node * DIMV + q * 4;
    float4 hv = *(const float4*)&h[idx];
    float4 ov;
    const float third = 1.0f / 3.0f;
    ov.x = hv.x * third; ov.y = hv.y * third;
    ov.z = hv.z * third; ov.w = hv.w * third;
    *(float4*)&out[idx] = ov;
    __half2 t0 = __floats2half2_rn(hv.x * nrm, hv.y * nrm);
    __half2 t1 = __floats2half2_rn(hv.z * nrm, hv.w * nrm);
    *(__half2*)&g_tmpA[idx]     = t0;
    *(__half2*)&g_tmpA[idx + 2] = t1;
}

// ---------------------------------------------------------------------------
// K_gather<LAST>: warp per node. Fused aggregate + epilogue.
//   sum = sum_{e in in(n)} half(tmp_src[src_e]) * w_e   (fp32 accum)
//   h   = sum * norm;  out += h/3;  if !LAST: tmpB = half(h * norm)
// Per edge: 32 lanes x 4B half2 = 128B of L2 gather traffic.
// ---------------------------------------------------------------------------
template <bool LAST>
__global__ void k_gather(float* __restrict__ out, int N) {
    const __half* __restrict__ tsrc = LAST ? g_tmpB : g_tmpA;
    int gw = (blockIdx.x * blockDim.x + threadIdx.x) >> 5;
    if (gw >= N) return;
    int lane = threadIdx.x & 31;
    int off = g_off[gw];
    int dg  = g_cnt[gw];
    float ax = 0.0f, ay = 0.0f;

    for (int base = 0; base < dg; base += 32) {
        int m = dg - base; if (m > 32) m = 32;
        float ex = 0.0f, ey = 0.0f;
        if (lane < m) {
            float2 ed = g_edges[off + base + lane];
            ex = ed.x; ey = ed.y;
        }
        if (m == 32) {
            #pragma unroll
            for (int k = 0; k < 32; k++) {
                int   s  = __float_as_int(__shfl_sync(0xffffffffu, ex, k));
                float sw = __shfl_sync(0xffffffffu, ey, k);
                __half2 hv = *(const __half2*)&tsrc[s * DIMV + lane * 2];
                float2 v = __half22float2(hv);
                ax = fmaf(v.x, sw, ax);
                ay = fmaf(v.y, sw, ay);
            }
        } else {
            for (int k = 0; k < m; k++) {
                int   s  = __float_as_int(__shfl_sync(0xffffffffu, ex, k));
                float sw = __shfl_sync(0xffffffffu, ey, k);
                __half2 hv = *(const __half2*)&tsrc[s * DIMV + lane * 2];
                float2 v = __half22float2(hv);
                ax = fmaf(v.x, sw, ax);
                ay = fmaf(v.y, sw, ay);
            }
        }
    }

    float nrm = g_norm[gw];
    float hx = ax * nrm, hy = ay * nrm;
    int idx = gw * DIMV + lane * 2;
    const float third = 1.0f / 3.0f;
    float2 o = *(float2*)&out[idx];
    o.x += hx * third; o.y += hy * third;
    *(float2*)&out[idx] = o;
    if (!LAST) {
        *(__half2*)&g_tmpB[idx] = __floats2half2_rn(hx * nrm, hy * nrm);
    }
}

// ---------------------------------------------------------------------------
// Launch
// ---------------------------------------------------------------------------
extern "C" void kernel_launch(void* const* d_in, const int* in_sizes, int n_in,
                              void* d_out, int out_size) {
    const float* h   = (const float*)d_in[0];
    const float* w   = (const float*)d_in[1];
    const int*   src = (const int*)d_in[2];
    const int*   dst = (const int*)d_in[3];
    float* out = (float*)d_out;

    const int N = in_sizes[0] / DIMV;   // 100000
    const int E = in_sizes[1];          // 1600000
    const int nch = (N + CHUNK - 1) / CHUNK;

    const int TB = 256;

    // CSR build
    k_zero<<<256, TB>>>(N);
    int dthreads = (E + 3) / 4;
    k_degcnt<<<(dthreads + TB - 1) / TB, TB>>>(w, dst, E);
    k_scan1<<<nch, CHUNK>>>(N);
    k_scan2<<<1, 256>>>(nch);
    k_scan3<<<nch, CHUNK>>>(N);
    k_place<<<(E + TB - 1) / TB, TB>>>(w, src, dst, E);

    // norm + layer-0 contribution
    int nt_node = N * (DIMV / 4);
    k_init<<<(nt_node + TB - 1) / TB, TB>>>(h, out, N);

    // Layers (warp per node, 8 warps/block)
    int gblocks = (N + 7) / 8;
    k_gather<false><<<gblocks, TB>>>(out, N);   // reads tmpA, writes tmpB
    k_gather<true><<<gblocks, TB>>>(out, N);    // reads tmpB
}